// round 8
// baseline (speedup 1.0000x reference)
#include <cuda_runtime.h>
#include <cooperative_groups.h>
namespace cg = cooperative_groups;

#define N_NODES 200000
#define C_IN 5

// Scratch in __device__ globals (zero-initialized at module load; g_cnt is
// re-zeroed within each call after use, so every call sees zeros).
__device__ int    g_cnt[N_NODES];     // in-degree (dst counts), excl. self-loop
__device__ float2 g_h[N_NODES];       // x @ W (unnormalized)
__device__ float2 g_hs[N_NODES];      // (x @ W) * dinv
__device__ float  g_dinv[N_NODES];    // rsqrt(deg)
__device__ float2 g_acc[N_NODES];     // sum of hs[src] per dst (init = self-loop term)

__device__ __forceinline__ void red_add_v2(float2* addr, float a, float b) {
    asm volatile("red.global.add.v2.f32 [%0], {%1, %2};"
                 :: "l"(addr), "f"(a), "f"(b)
                 : "memory");
}

__device__ __forceinline__ int4 ldg_cs_int4(const int4* p) {
    int4 v;
    asm volatile("ld.global.cs.v4.s32 {%0,%1,%2,%3}, [%4];"
                 : "=r"(v.x), "=r"(v.y), "=r"(v.z), "=r"(v.w) : "l"(p));
    return v;
}

__device__ __forceinline__ float2 ldg_ca_f2(const float2* p) {
    float2 v;
    asm volatile("ld.global.ca.v2.f32 {%0,%1}, [%2];"
                 : "=f"(v.x), "=f"(v.y) : "l"(p));
    return v;
}

__global__ void __launch_bounds__(256) k_fused(const float* __restrict__ x,
                                               const int4* __restrict__ src4,
                                               const int4* __restrict__ dst4,
                                               const float* __restrict__ W,
                                               const float* __restrict__ b,
                                               float* __restrict__ out,
                                               int n, int E4) {
    cg::grid_group grid = cg::this_grid();
    const int tid = blockIdx.x * blockDim.x + threadIdx.x;
    const int nth = gridDim.x * blockDim.x;

    // ---- Phase 1: in-degree count (edges) + h = x@W (nodes, independent) ----
    for (int i = tid; i < E4; i += nth) {
        int4 d = ldg_cs_int4(dst4 + i);
        atomicAdd(&g_cnt[d.x], 1);
        atomicAdd(&g_cnt[d.y], 1);
        atomicAdd(&g_cnt[d.z], 1);
        atomicAdd(&g_cnt[d.w], 1);
    }
    {
        float w0 = W[0], w1 = W[1], w2 = W[2], w3 = W[3], w4 = W[4];
        float w5 = W[5], w6 = W[6], w7 = W[7], w8 = W[8], w9 = W[9];
        for (int i = tid; i < n; i += nth) {
            const float* xr = x + (size_t)i * C_IN;
            float x0 = xr[0], x1 = xr[1], x2 = xr[2], x3 = xr[3], x4 = xr[4];
            float h0 = x0 * w0 + x1 * w2 + x2 * w4 + x3 * w6 + x4 * w8;
            float h1 = x0 * w1 + x1 * w3 + x2 * w5 + x3 * w7 + x4 * w9;
            g_h[i] = make_float2(h0, h1);
        }
    }
    __threadfence();
    grid.sync();

    // ---- Phase 2: dinv, hs, acc init; re-zero cnt for next call ----
    for (int i = tid; i < n; i += nth) {
        int c = g_cnt[i];
        g_cnt[i] = 0;
        float dinv = rsqrtf((float)(c + 1));    // +1 self-loop
        float2 h = g_h[i];
        float2 hs = make_float2(h.x * dinv, h.y * dinv);
        g_hs[i] = hs;
        g_dinv[i] = dinv;
        g_acc[i] = hs;    // self-loop term (dinv[dst] applied in phase 4)
    }
    __threadfence();
    grid.sync();

    // ---- Phase 3: edge scatter (gather hs[src] + fused v2 RED into acc[dst]) ----
    for (int i = tid; i < E4; i += nth) {
        int4 s = ldg_cs_int4(src4 + i);
        int4 d = ldg_cs_int4(dst4 + i);
        float2 a = ldg_ca_f2(&g_hs[s.x]);
        float2 bb = ldg_ca_f2(&g_hs[s.y]);
        float2 c = ldg_ca_f2(&g_hs[s.z]);
        float2 e = ldg_ca_f2(&g_hs[s.w]);
        red_add_v2(&g_acc[d.x], a.x, a.y);
        red_add_v2(&g_acc[d.y], bb.x, bb.y);
        red_add_v2(&g_acc[d.z], c.x, c.y);
        red_add_v2(&g_acc[d.w], e.x, e.y);
    }
    __threadfence();
    grid.sync();

    // ---- Phase 4: finalize + integrate + clip ----
    {
        float b0 = b[0], b1 = b[1];
        for (int i = tid; i < n; i += nth) {
            float2 a = g_acc[i];
            float dinv = g_dinv[i];
            float acc0 = (a.x * dinv + b0) * 0.01f;
            float acc1 = (a.y * dinv + b1) * 0.01f;
            const float* xr = x + (size_t)i * C_IN;
            float v0 = fminf(fmaxf(xr[2] + acc0, -0.1f), 0.1f);
            float v1 = fminf(fmaxf(xr[3] + acc1, -0.1f), 0.1f);
            float p0 = fminf(fmaxf(xr[0] + v0, -1.0f), 1.0f);
            float p1 = fminf(fmaxf(xr[1] + v1, -1.0f), 1.0f);
            float* orow = out + (size_t)i * C_IN;
            orow[0] = p0;
            orow[1] = p1;
            orow[2] = v0;
            orow[3] = v1;
            orow[4] = xr[4];
        }
    }
}

extern "C" void kernel_launch(void* const* d_in, const int* in_sizes, int n_in,
                              void* d_out, int out_size) {
    const float* x  = (const float*)d_in[0];   // [N,5]
    const int*   ei = (const int*)d_in[1];     // [2,E]: src row then dst row
    const float* W  = (const float*)d_in[2];   // [5,2]
    const float* b  = (const float*)d_in[3];   // [2]
    float* out = (float*)d_out;

    int n = in_sizes[0] / C_IN;     // 200000
    int E = in_sizes[1] / 2;        // 12800000 (divisible by 4)
    const int* src = ei;
    const int* dst = ei + E;
    int E4 = E / 4;

    const int T = 256;

    // Size the persistent grid to exactly the co-resident capacity.
    int dev = 0;
    cudaGetDevice(&dev);
    int sms = 148;
    cudaDeviceGetAttribute(&sms, cudaDevAttrMultiProcessorCount, dev);
    int blocksPerSm = 1;
    cudaOccupancyMaxActiveBlocksPerMultiprocessor(&blocksPerSm, k_fused, T, 0);
    int grid = sms * blocksPerSm;

    const int4* src4 = (const int4*)src;
    const int4* dst4 = (const int4*)dst;

    void* args[] = { (void*)&x, (void*)&src4, (void*)&dst4,
                     (void*)&W, (void*)&b, (void*)&out,
                     (void*)&n, (void*)&E4 };
    cudaLaunchCooperativeKernel((void*)k_fused, dim3(grid), dim3(T), args, 0, 0);
}

// round 9
// speedup vs baseline: 1.4748x; 1.4748x over previous
#include <cuda_runtime.h>

#define N_NODES 200000
#define C_IN 5
#define T_BLK 256

// Scratch in __device__ globals (zero-initialized at module load; g_cnt is
// re-zeroed in k_prep after use, so every call sees zeros).
__device__ int    g_cnt[N_NODES];     // in-degree (dst counts), excl. self-loop
__device__ float2 g_h[N_NODES];       // x @ W (unnormalized)
__device__ float2 g_hs[N_NODES];      // (x @ W) * dinv
__device__ float  g_dinv[N_NODES];    // rsqrt(deg)
__device__ float2 g_acc[N_NODES];     // sum of hs[src] per dst (init = self-loop term)

__device__ __forceinline__ void red_add_v2(float2* addr, float a, float b) {
    asm volatile("red.global.add.v2.f32 [%0], {%1, %2};"
                 :: "l"(addr), "f"(a), "f"(b)
                 : "memory");
}

__device__ __forceinline__ int4 ldg_cs_int4(const int4* p) {
    int4 v;
    asm volatile("ld.global.cs.v4.s32 {%0,%1,%2,%3}, [%4];"
                 : "=r"(v.x), "=r"(v.y), "=r"(v.z), "=r"(v.w) : "l"(p));
    return v;
}

__device__ __forceinline__ float2 ldg_ca_f2(const float2* p) {
    float2 v;
    asm volatile("ld.global.ca.v2.f32 {%0,%1}, [%2];"
                 : "=f"(v.x), "=f"(v.y) : "l"(p));
    return v;
}

// Heterogeneous grid, h-blocks FIRST (no straggler tail):
//   blocks [0, gN)        : h = x@W via smem-staged coalesced loads
//   blocks [gN, gN+gE4)   : in-degree count, 4 edges/thread
__global__ void __launch_bounds__(T_BLK) k_count_h(const int4* __restrict__ dst4, int E4,
                                                   const float* __restrict__ x,
                                                   const float* __restrict__ W,
                                                   int n, int gN) {
    if (blockIdx.x < (unsigned)gN) {
        __shared__ float sx[T_BLK * C_IN];
        int base = blockIdx.x * T_BLK * C_IN;          // element base into x
        int lim = n * C_IN;
        #pragma unroll
        for (int j = threadIdx.x; j < T_BLK * C_IN; j += T_BLK) {
            int g = base + j;
            sx[j] = (g < lim) ? x[g] : 0.0f;
        }
        __syncthreads();
        int i = blockIdx.x * T_BLK + threadIdx.x;
        if (i < n) {
            const float* xr = &sx[threadIdx.x * C_IN];
            float x0 = xr[0], x1 = xr[1], x2 = xr[2], x3 = xr[3], x4 = xr[4];
            float h0 = x0 * W[0] + x1 * W[2] + x2 * W[4] + x3 * W[6] + x4 * W[8];
            float h1 = x0 * W[1] + x1 * W[3] + x2 * W[5] + x3 * W[7] + x4 * W[9];
            g_h[i] = make_float2(h0, h1);
        }
    } else {
        int i = (blockIdx.x - gN) * T_BLK + threadIdx.x;
        if (i < E4) {
            int4 d = ldg_cs_int4(dst4 + i);
            atomicAdd(&g_cnt[d.x], 1);
            atomicAdd(&g_cnt[d.y], 1);
            atomicAdd(&g_cnt[d.z], 1);
            atomicAdd(&g_cnt[d.w], 1);
        }
    }
    cudaTriggerProgrammaticLaunchCompletion();
}

// Scratch-only pass: dinv, hs, acc init; re-zero cnt. All coalesced.
__global__ void k_prep(int n) {
    int i = blockIdx.x * blockDim.x + threadIdx.x;
    cudaGridDependencySynchronize();
    if (i < n) {
        int c = g_cnt[i];
        g_cnt[i] = 0;                                // re-arm for next call
        float dinv = rsqrtf((float)(c + 1));         // +1 self-loop
        float2 h = g_h[i];
        float2 hs = make_float2(h.x * dinv, h.y * dinv);
        g_hs[i] = hs;
        g_dinv[i] = dinv;
        g_acc[i] = hs;   // self-loop term (dinv[dst] applied at finalize)
    }
    cudaTriggerProgrammaticLaunchCompletion();
}

// 4 edges/thread: random gather (.ca) + fused v2 RED per edge.
__global__ void __launch_bounds__(T_BLK) k_scatter(const int4* __restrict__ src4,
                                                   const int4* __restrict__ dst4,
                                                   int E4) {
    int i = blockIdx.x * blockDim.x + threadIdx.x;
    cudaGridDependencySynchronize();
    if (i < E4) {
        int4 s = ldg_cs_int4(src4 + i);
        int4 d = ldg_cs_int4(dst4 + i);
        float2 a = ldg_ca_f2(&g_hs[s.x]);
        float2 b = ldg_ca_f2(&g_hs[s.y]);
        float2 c = ldg_ca_f2(&g_hs[s.z]);
        float2 e = ldg_ca_f2(&g_hs[s.w]);
        red_add_v2(&g_acc[d.x], a.x, a.y);
        red_add_v2(&g_acc[d.y], b.x, b.y);
        red_add_v2(&g_acc[d.z], c.x, c.y);
        red_add_v2(&g_acc[d.w], e.x, e.y);
    }
    cudaTriggerProgrammaticLaunchCompletion();
}

// Finalize with smem-staged coalesced read of x and write of out.
__global__ void __launch_bounds__(T_BLK) k_final(const float* __restrict__ x,
                                                 const float* __restrict__ b,
                                                 float* __restrict__ out,
                                                 int n) {
    __shared__ float sb[T_BLK * C_IN];
    cudaGridDependencySynchronize();
    int base = blockIdx.x * T_BLK * C_IN;
    int lim = n * C_IN;
    #pragma unroll
    for (int j = threadIdx.x; j < T_BLK * C_IN; j += T_BLK) {
        int g = base + j;
        sb[j] = (g < lim) ? x[g] : 0.0f;
    }
    __syncthreads();

    int i = blockIdx.x * T_BLK + threadIdx.x;
    float p0 = 0, p1 = 0, v0 = 0, v1 = 0, x4 = 0;
    if (i < n) {
        const float* xr = &sb[threadIdx.x * C_IN];
        float2 a = g_acc[i];
        float dinv = g_dinv[i];
        float acc0 = (a.x * dinv + b[0]) * 0.01f;
        float acc1 = (a.y * dinv + b[1]) * 0.01f;
        v0 = fminf(fmaxf(xr[2] + acc0, -0.1f), 0.1f);
        v1 = fminf(fmaxf(xr[3] + acc1, -0.1f), 0.1f);
        p0 = fminf(fmaxf(xr[0] + v0, -1.0f), 1.0f);
        p1 = fminf(fmaxf(xr[1] + v1, -1.0f), 1.0f);
        x4 = xr[4];
    }
    __syncthreads();
    {
        float* orow = &sb[threadIdx.x * C_IN];
        orow[0] = p0; orow[1] = p1; orow[2] = v0; orow[3] = v1; orow[4] = x4;
    }
    __syncthreads();
    #pragma unroll
    for (int j = threadIdx.x; j < T_BLK * C_IN; j += T_BLK) {
        int g = base + j;
        if (g < lim) out[g] = sb[j];
    }
}

template <typename... Args>
static inline void launch_pdl(void (*kern)(Args...), int grid, int block,
                              Args... args) {
    cudaLaunchConfig_t cfg = {};
    cfg.gridDim = dim3(grid);
    cfg.blockDim = dim3(block);
    cudaLaunchAttribute attr[1];
    attr[0].id = cudaLaunchAttributeProgrammaticStreamSerialization;
    attr[0].val.programmaticStreamSerializationAllowed = 1;
    cfg.attrs = attr;
    cfg.numAttrs = 1;
    cudaLaunchKernelEx(&cfg, kern, args...);
}

extern "C" void kernel_launch(void* const* d_in, const int* in_sizes, int n_in,
                              void* d_out, int out_size) {
    const float* x  = (const float*)d_in[0];   // [N,5]
    const int*   ei = (const int*)d_in[1];     // [2,E]: src row then dst row
    const float* W  = (const float*)d_in[2];   // [5,2]
    const float* b  = (const float*)d_in[3];   // [2]
    float* out = (float*)d_out;

    int n = in_sizes[0] / C_IN;     // 200000
    int E = in_sizes[1] / 2;        // 12800000 (divisible by 4)
    const int* src = ei;
    const int* dst = ei + E;
    int E4 = E / 4;

    int gN  = (n + T_BLK - 1) / T_BLK;
    int gE4 = (E4 + T_BLK - 1) / T_BLK;

    k_count_h<<<gN + gE4, T_BLK>>>((const int4*)dst, E4, x, W, n, gN);
    launch_pdl(k_prep, gN, T_BLK, n);
    launch_pdl(k_scatter, gE4, T_BLK, (const int4*)src, (const int4*)dst, E4);
    launch_pdl(k_final, gN, T_BLK, x, b, out, n);
}